// round 17
// baseline (speedup 1.0000x reference)
#include <cuda_runtime.h>

// x: (128, 32, 2, 64, 64) fp32 -> 4096 tiles of (2, 64, 64).
// plaq[i][j] = t0[i][j] + t1[(i+1)%64][j] - t0[i][(j+1)%64] - t1[i][j]
// out[tile] = mean(cos(plaq))
//
// R16 winning body (512 thr/CTA, telescoped t1 loads: 2x t0 __ldcs-streamed +
// 3x t1 default/L2-resident per thread, in-register j+1 roll via lane
// shuffle) with a BARRIER-FREE epilogue: each warp shuffle-reduces its 512
// elements and lane 0 fires one atomicAdd (RED.F32, no return) into out[t].
// No smem, no __syncthreads, no second reduction -> warp lifetime no longer
// includes the max-warp barrier skew. out is zeroed by a tiny first kernel
// (d_out is poisoned by the harness).

#define THREADS 512

__global__ void zero_out_kernel(float* __restrict__ out)
{
    out[blockIdx.x * 256 + threadIdx.x] = 0.0f;
}

__global__ __launch_bounds__(THREADS, 4) void plaq_trace_atomic_kernel(
    const float4* __restrict__ x4, float* __restrict__ out)
{
    const int t = blockIdx.x;
    const float4* __restrict__ t0 = x4 + (size_t)t * 2048;  // 1024 float4 each
    const float4* __restrict__ t1 = t0 + 1024;

    const int tid  = threadIdx.x;
    const int lane = tid & 31;
    const int jg   = tid & 15;          // column group 0..15
    const int r0   = (tid >> 4) * 2;    // first of two consecutive rows
    const int src  = (lane & 16) | ((lane + 1) & 15);  // right-neighbor lane

    // Front-batched independent loads: 2x t0 (streamed) + 3x t1 (default).
    float4 A0[2], A1[3];
    #pragma unroll
    for (int u = 0; u < 2; u++)
        A0[u] = __ldcs(t0 + (r0 + u) * 16 + jg);
    #pragma unroll
    for (int u = 0; u < 3; u++)
        A1[u] = t1[(((r0 + u) & 63) << 4) + jg];

    float sum = 0.0f;
    #pragma unroll
    for (int u = 0; u < 2; u++) {
        const float4 a0 = A0[u];
        const float4 a1 = A1[u];
        const float4 b1 = A1[u + 1];               // telescoped row roll
        const float nx = __shfl_sync(0xFFFFFFFFu, a0.x, src);
        sum += __cosf(a0.x + b1.x - a0.y - a1.x);
        sum += __cosf(a0.y + b1.y - a0.z - a1.y);
        sum += __cosf(a0.z + b1.z - a0.w - a1.z);
        sum += __cosf(a0.w + b1.w - nx   - a1.w);
    }

    // Warp-only reduction, then one fire-and-forget atomic per warp.
    #pragma unroll
    for (int off = 16; off > 0; off >>= 1)
        sum += __shfl_xor_sync(0xFFFFFFFFu, sum, off);

    if (lane == 0)
        atomicAdd(out + t, sum * (1.0f / 4096.0f));
}

extern "C" void kernel_launch(void* const* d_in, const int* in_sizes, int n_in,
                              void* d_out, int out_size)
{
    const float4* x4 = (const float4*)d_in[0];
    float* out = (float*)d_out;
    zero_out_kernel<<<16, 256>>>(out);             // 4096 floats
    plaq_trace_atomic_kernel<<<4096, THREADS>>>(x4, out);
}